// round 14
// baseline (speedup 1.0000x reference)
#include <cuda_runtime.h>
#include <cuda_bf16.h>
#include <math.h>
#include <stdint.h>

#define Nn 4096
#define Dd 384
#define Ee 131072
#define Hh 8
#define DHh 48
#define Ll 3
#define SEC (Hh * Nn * 48)

// ---------------- fast exp2 on the FMA pipe ----------------------------------
__device__ __forceinline__ float fexp2(float t) {
    t = fmaxf(t, -126.0f);
    float r = t + 12582912.0f;
    int n = __float_as_int(r) - 0x4B400000;
    float f = t - (r - 12582912.0f);
    float p = 1.8775767e-3f;
    p = fmaf(p, f, 8.9893397e-3f);
    p = fmaf(p, f, 5.5826318e-2f);
    p = fmaf(p, f, 2.4015361e-1f);
    p = fmaf(p, f, 6.9315308e-1f);
    p = fmaf(p, f, 1.0f);
    return __int_as_float(__float_as_int(p) + (n << 23));
}

// pack two fp32 -> bf16x2 word (low half = f0)
__device__ __forceinline__ uint32_t bf2(float f0, float f1) {
    uint32_t w;
    asm("cvt.rn.bf16x2.f32 %0, %1, %2;" : "=r"(w) : "f"(f1), "f"(f0));
    return w;
}
__device__ __forceinline__ float lof(uint32_t w) { return __uint_as_float(w << 16); }
__device__ __forceinline__ float hif(uint32_t w) { return __uint_as_float(w & 0xFFFF0000u); }

__device__ __forceinline__ uint32_t s2u(const void* p) {
    return (uint32_t)__cvta_generic_to_shared(p);
}
__device__ __forceinline__ void ldmx4(uint32_t r[4], uint32_t a) {
    asm volatile("ldmatrix.sync.aligned.m8n8.x4.shared.b16 {%0,%1,%2,%3}, [%4];"
                 : "=r"(r[0]), "=r"(r[1]), "=r"(r[2]), "=r"(r[3]) : "r"(a));
}
__device__ __forceinline__ void mma_bf16(float d[4], const uint32_t a[4],
                                         uint32_t b0, uint32_t b1) {
    asm volatile("mma.sync.aligned.m16n8k16.row.col.f32.bf16.bf16.f32 "
                 "{%0,%1,%2,%3}, {%4,%5,%6,%7}, {%8,%9}, {%0,%1,%2,%3};"
                 : "+f"(d[0]), "+f"(d[1]), "+f"(d[2]), "+f"(d[3])
                 : "r"(a[0]), "r"(a[1]), "r"(a[2]), "r"(a[3]), "r"(b0), "r"(b1));
}
__device__ __forceinline__ void cpasync16(uint32_t dst, const void* src) {
    asm volatile("cp.async.cg.shared.global [%0], [%1], 16;" :: "r"(dst), "l"(src));
}

// ---------------- scratch ----------------------------------------------------
__device__ __align__(16) float g_h[Nn * Dd];
__device__ __align__(16) float g_qkv[Nn * 3 * Dd];   // fp32 q|k|v per node
__device__ int   g_deg[Nn];
__device__ float g_degf[Nn];
__device__ int   g_rowptr[Nn + 1];
__device__ int   g_fillpos[Nn];
__device__ int   g_colidx[Ee];
// bf16 split-3 activation buffers, layout [plane][node*384+col]
__device__ __align__(16) unsigned short g_sA[3][Nn * Dd];  // gather out (agg)
__device__ __align__(16) unsigned short g_sB[3][Nn * Dd];  // conv out  (hnew)
__device__ __align__(16) unsigned short g_sC[3][Nn * Dd];  // flash out (o)
// bf16 split-3 weights
#define WTOT 1032192
#define OFF_CONV(l) ((l) * Dd * Dd)
#define OFF_WIN (3 * Dd * Dd)
#define OFF_WAO (3 * Dd * Dd + 3 * Dd * Dd)
__device__ __align__(16) unsigned short g_ws[3][WTOT];
// flash-side Q/K split-2 tensors: [plane][head][node][48]
__device__ __align__(16) unsigned short g_qs[2 * SEC];   // Q hi/lo (scaled)
__device__ __align__(16) unsigned short g_kvs[2 * SEC];  // K hi/lo

// split (v0,v1) into 3 bf16x2 planes of a [3][...] array
template <typename PT>
__device__ __forceinline__ void split3_pair(PT planes, int idx, float v0, float v1) {
    uint32_t w0 = bf2(v0, v1);
    *(uint32_t*)&planes[0][idx] = w0;
    float r0 = v0 - lof(w0), r1 = v1 - hif(w0);
    uint32_t w1 = bf2(r0, r1);
    *(uint32_t*)&planes[1][idx] = w1;
    *(uint32_t*)&planes[2][idx] = bf2(r0 - lof(w1), r1 - hif(w1));
}
__device__ __forceinline__ void split2s(unsigned short* base, int stride, int idx,
                                        float v0, float v1) {
    uint32_t w0 = bf2(v0, v1);
    *(uint32_t*)&base[idx] = w0;
    *(uint32_t*)&base[stride + idx] = bf2(v0 - lof(w0), v1 - hif(w0));
}

// ---------------- CSR build --------------------------------------------------
__global__ void k_zero_deg() {
    int i = blockIdx.x * blockDim.x + threadIdx.x;
    if (i < Nn) g_deg[i] = 0;
}
__global__ void k_hist(const int* __restrict__ ei) {
    int e = blockIdx.x * blockDim.x + threadIdx.x;
    if (e < Ee) atomicAdd(&g_deg[ei[e]], 1);
}
__global__ void k_scan() {
    __shared__ int s[1024];
    int tid = threadIdx.x;
    int b = tid * 4;
    int v0 = g_deg[b], v1 = g_deg[b + 1], v2 = g_deg[b + 2], v3 = g_deg[b + 3];
    int p1 = v0 + v1, p2 = p1 + v2, p3 = p2 + v3;
    s[tid] = p3;
    __syncthreads();
    for (int off = 1; off < 1024; off <<= 1) {
        int t = (tid >= off) ? s[tid - off] : 0;
        __syncthreads();
        if (tid >= off) s[tid] += t;
        __syncthreads();
    }
    int prev = tid ? s[tid - 1] : 0;
    int e0 = prev, e1 = prev + v0, e2 = prev + p1, e3 = prev + p2;
    g_rowptr[b] = e0; g_rowptr[b + 1] = e1; g_rowptr[b + 2] = e2; g_rowptr[b + 3] = e3;
    g_fillpos[b] = e0; g_fillpos[b + 1] = e1; g_fillpos[b + 2] = e2; g_fillpos[b + 3] = e3;
    g_degf[b] = (float)v0; g_degf[b + 1] = (float)v1;
    g_degf[b + 2] = (float)v2; g_degf[b + 3] = (float)v3;
    if (tid == 1023) g_rowptr[Nn] = s[1023];
}
__global__ void k_fill(const int* __restrict__ ei) {
    int e = blockIdx.x * blockDim.x + threadIdx.x;
    if (e < Ee) {
        int dst = ei[e];
        int src = ei[Ee + e];
        int pos = atomicAdd(&g_fillpos[dst], 1);
        g_colidx[pos] = src;
    }
}
__global__ void k_copy(const float* __restrict__ emb) {
    int i = blockIdx.x * blockDim.x + threadIdx.x;
    if (i < Nn * Dd / 4)
        ((float4*)g_h)[i] = ((const float4*)emb)[i];
}

// ---------------- weight split (once per launch) ------------------------------
__global__ __launch_bounds__(256) void k_wsplit(const float* __restrict__ src,
                                                int dstoff, int n4) {
    int i = blockIdx.x * 256 + threadIdx.x;
    if (i >= n4) return;
    float4 x = ((const float4*)src)[i];
    int idx = dstoff + i * 4;
    split3_pair(g_ws, idx, x.x, x.y);
    split3_pair(g_ws, idx + 2, x.z, x.w);
}

// ---------------- neighbor aggregation -> split-3 bf16 ------------------------
__global__ __launch_bounds__(256) void k_gather() {
    int warp = (blockIdx.x * blockDim.x + threadIdx.x) >> 5;
    int lane = threadIdx.x & 31;
    if (warp >= Nn) return;
    int pbeg = g_rowptr[warp], pend = g_rowptr[warp + 1];
    float4 a0 = {0, 0, 0, 0}, a1 = a0, a2 = a0;
    for (int p = pbeg; p < pend; p++) {
        int src = g_colidx[p];
        const float4* r = (const float4*)(g_h + src * Dd);
        float4 x;
        x = r[lane];      a0.x += x.x; a0.y += x.y; a0.z += x.z; a0.w += x.w;
        x = r[lane + 32]; a1.x += x.x; a1.y += x.y; a1.z += x.z; a1.w += x.w;
        x = r[lane + 64]; a2.x += x.x; a2.y += x.y; a2.z += x.z; a2.w += x.w;
    }
    int base = warp * Dd + lane * 4;
    split3_pair(g_sA, base, a0.x, a0.y);
    split3_pair(g_sA, base + 2, a0.z, a0.w);
    split3_pair(g_sA, base + 128, a1.x, a1.y);
    split3_pair(g_sA, base + 130, a1.z, a1.w);
    split3_pair(g_sA, base + 256, a2.x, a2.y);
    split3_pair(g_sA, base + 258, a2.z, a2.w);
}

// ---------------- pipelined mma.sync GEMM: C = A * B^T + epilogue -------------
// MODE 0: A=g_sA -> split-3 g_sB, bias*degf                 (conv)
// MODE 1: A=g_sB -> fp32 g_qkv + split-2 Q(scaled)/K        (qkv)
// MODE 2: A=g_sC -> fp32 g_h, bias+residual+relu            (attn out)
#define GM_BUF 36864
#define GM_SMEM 73728

template <int MODE>
__global__ __launch_bounds__(256, 2) void k_gemm_mma(int woff,
                                                     const float* __restrict__ bias) {
    extern __shared__ __align__(128) char sm[];
    uint32_t smb = s2u(sm);
    const int tid = threadIdx.x, lane = tid & 31, w = tid >> 5;
    const int row0 = blockIdx.y * 128, col0 = blockIdx.x * 64;
    const int l15 = lane & 15, l7 = lane & 7;
    const int lhi = lane >> 4, lmid = (lane >> 3) & 1;

    float of[8][4];
#pragma unroll
    for (int i = 0; i < 8; i++)
#pragma unroll
        for (int j = 0; j < 4; j++) of[i][j] = 0.f;

    auto stage = [&](int kc, int buf) {
        uint32_t bb = smb + buf * GM_BUF;
        for (int i = tid; i < 1536; i += 256) {
            int arr = i >> 9, rem = i & 511;
            int row = rem >> 2, ch = rem & 3;
            const unsigned short* ap = (MODE == 0) ? g_sA[arr]
                                     : (MODE == 1) ? g_sB[arr] : g_sC[arr];
            cpasync16(bb + arr * 8192 + row * 64 + ((ch ^ ((row >> 1) & 3)) * 16),
                      ap + (row0 + row) * 384 + kc * 32 + ch * 8);
        }
        for (int i = tid; i < 768; i += 256) {
            int arr = i >> 8, rem = i & 255;
            int n = rem >> 2, ch = rem & 3;
            cpasync16(bb + 24576 + arr * 4096 + n * 64 + ((ch ^ ((n >> 1) & 3)) * 16),
                      g_ws[arr] + woff + (col0 + n) * 384 + kc * 32 + ch * 8);
        }
        asm volatile("cp.async.commit_group;" ::: "memory");
    };

    stage(0, 0);
    for (int kc = 0; kc < 12; kc++) {
        int buf = kc & 1;
        if (kc + 1 < 12) stage(kc + 1, buf ^ 1);
        else asm volatile("cp.async.commit_group;" ::: "memory");
        asm volatile("cp.async.wait_group 1;" ::: "memory");
        __syncthreads();

        uint32_t bb = smb + buf * GM_BUF;
#pragma unroll
        for (int asp = 0; asp < 3; asp++) {
            uint32_t Af[2][4];
#pragma unroll
            for (int kst = 0; kst < 2; kst++) {
                int row = 16 * w + l15, ch = 2 * kst + lhi;
                ldmx4(Af[kst], bb + asp * 8192 + row * 64 +
                               ((ch ^ ((row >> 1) & 3)) * 16));
            }
#pragma unroll
            for (int bsp = 0; bsp < 3; bsp++) {
                if (bsp <= 2 - asp) {
#pragma unroll
                    for (int kst = 0; kst < 2; kst++) {
#pragma unroll
                        for (int np = 0; np < 4; np++) {
                            int key = 8 * (2 * np + lhi) + l7, ch = 2 * kst + lmid;
                            uint32_t r[4];
                            ldmx4(r, bb + 24576 + bsp * 4096 + key * 64 +
                                     ((ch ^ ((key >> 1) & 3)) * 16));
                            mma_bf16(of[2 * np], Af[kst], r[0], r[1]);
                            mma_bf16(of[2 * np + 1], Af[kst], r[2], r[3]);
                        }
                    }
                }
            }
        }
        __syncthreads();
    }

    // epilogue
    const float qscale = 0.14433756729740643f * 1.4426950408889634f;
    int r0 = row0 + 16 * w + (lane >> 2), r1 = r0 + 8;
    int cbl = (lane & 3) * 2;
    float dg0 = (MODE == 0) ? g_degf[r0] : 1.f;
    float dg1 = (MODE == 0) ? g_degf[r1] : 1.f;
#pragma unroll
    for (int nt = 0; nt < 8; nt++) {
        int n = col0 + nt * 8 + cbl;
        float b0 = bias[n], b1 = bias[n + 1];
        float v00 = of[nt][0] + b0 * dg0, v01 = of[nt][1] + b1 * dg0;
        float v10 = of[nt][2] + b0 * dg1, v11 = of[nt][3] + b1 * dg1;
        if (MODE == 0) {
            split3_pair(g_sB, r0 * 384 + n, v00, v01);
            split3_pair(g_sB, r1 * 384 + n, v10, v11);
        } else if (MODE == 1) {
            *(float2*)&g_qkv[r0 * 1152 + n] = make_float2(v00, v01);
            *(float2*)&g_qkv[r1 * 1152 + n] = make_float2(v10, v11);
            int sec = n / 384;
            int wn = n - sec * 384;
            int hd = wn / 48, d = wn - hd * 48;
            int i0 = (hd * Nn + r0) * 48 + d;
            int i1 = (hd * Nn + r1) * 48 + d;
            if (sec == 0) {
                split2s(g_qs, SEC, i0, v00 * qscale, v01 * qscale);
                split2s(g_qs, SEC, i1, v10 * qscale, v11 * qscale);
            } else if (sec == 1) {
                split2s(g_kvs, SEC, i0, v00, v01);
                split2s(g_kvs, SEC, i1, v10, v11);
            }
        } else {
            float2 h0 = *(const float2*)&g_h[r0 * 384 + n];
            float2 h1 = *(const float2*)&g_h[r1 * 384 + n];
            *(float2*)&g_h[r0 * 384 + n] =
                make_float2(fmaxf(v00 + h0.x, 0.f), fmaxf(v01 + h0.y, 0.f));
            *(float2*)&g_h[r1 * 384 + n] =
                make_float2(fmaxf(v10 + h1.x, 0.f), fmaxf(v11 + h1.y, 0.f));
        }
    }
}

// ---------------- shortlist flash attention -----------------------------------
// Pass A: approx S via 3 bf16 split terms {00,01,10}; per-row running max m̂;
//         shortlist keys with Ŝ >= m̂ - (33 + |m̂|*1e-3) into smem lists.
// Pass B: thread-per-row exact fp32 softmax over shortlist (online rescale).
//         Overflow rows (count > CAP) fall back to full 4096-key scan.
#define CAP 48
#define FL2_KBUF 16384
#define FL2_LISTS 32768
#define FL2_CNT (FL2_LISTS + 128 * CAP * 4)   // 57344
#define FL2_SMEM (FL2_CNT + 512)              // 57856

__device__ __forceinline__ void flash2_stage(uint32_t smb, int hN, int k0,
                                             int buf, int tid) {
    for (int i = tid; i < 768; i += 256) {
        int arr = i / 384, rem = i - arr * 384;
        int row = rem / 6, c = rem - row * 6;
        cpasync16(smb + buf * FL2_KBUF + arr * 8192 + row * 128 +
                      ((c * 16) ^ ((row & 7) * 16)),
                  g_kvs + arr * SEC + (hN + k0 + row) * 48 + c * 8);
    }
    asm volatile("cp.async.commit_group;" ::: "memory");
}

__global__ __launch_bounds__(256, 2) void k_flash_sel() {
    extern __shared__ __align__(128) char sm[];
    uint32_t smb = s2u(sm);
    int* lists = (int*)(sm + FL2_LISTS);
    int* cnt = (int*)(sm + FL2_CNT);
    const int tid = threadIdx.x, lane = tid & 31, w = tid >> 5;
    const int head = blockIdx.y, q0 = blockIdx.x * 128;
    const int hN = head * Nn;
    const int l7 = lane & 7;
    const int lhi = lane >> 4, lmid = (lane >> 3) & 1;
    const float qscale = 0.14433756729740643f * 1.4426950408889634f;

    if (tid < 128) cnt[tid] = 0;

    // Q A-fragments (split planes 0,1) direct from global
    uint32_t qf[2][3][4];
    {
        int rl = 16 * w + (lane >> 2);
        int cq = (lane & 3) * 2;
#pragma unroll
        for (int qs = 0; qs < 2; qs++) {
            const unsigned short* qp = g_qs + qs * SEC + (hN + q0) * 48;
#pragma unroll
            for (int ks = 0; ks < 3; ks++) {
                int c = 16 * ks + cq;
                qf[qs][ks][0] = *(const uint32_t*)&qp[rl * 48 + c];
                qf[qs][ks][1] = *(const uint32_t*)&qp[(rl + 8) * 48 + c];
                qf[qs][ks][2] = *(const uint32_t*)&qp[rl * 48 + c + 8];
                qf[qs][ks][3] = *(const uint32_t*)&qp[(rl + 8) * 48 + c + 8];
            }
        }
    }

    float m0 = -1e30f, m1 = -1e30f;
    const int r0loc = 16 * w + (lane >> 2), r1loc = r0loc + 8;
    const int cb = (lane & 3) * 2;

    flash2_stage(smb, hN, 0, 0, tid);

    for (int kt = 0; kt < 64; kt++) {
        int buf = kt & 1;
        uint32_t kvb = smb + buf * FL2_KBUF;
        if (kt + 1 < 64) flash2_stage(smb, hN, (kt + 1) * 64, buf ^ 1, tid);
        else asm volatile("cp.async.commit_group;" ::: "memory");
        asm volatile("cp.async.wait_group 1;" ::: "memory");
        __syncthreads();

        float sf[8][4];
#pragma unroll
        for (int nt = 0; nt < 8; nt++)
#pragma unroll
            for (int j = 0; j < 4; j++) sf[nt][j] = 0.f;

#pragma unroll
        for (int ks = 0; ks < 3; ks++) {
#pragma unroll
            for (int kk = 0; kk < 2; kk++) {
                uint32_t Bf[8][2];
#pragma unroll
                for (int np = 0; np < 4; np++) {
                    int key = 8 * (2 * np + lhi) + l7;
                    int ch = 2 * ks + lmid;
                    uint32_t r[4];
                    ldmx4(r, kvb + kk * 8192 + key * 128 +
                             ((ch * 16) ^ ((key & 7) * 16)));
                    Bf[2 * np][0] = r[0]; Bf[2 * np][1] = r[1];
                    Bf[2 * np + 1][0] = r[2]; Bf[2 * np + 1][1] = r[3];
                }
                int nq = (kk == 0) ? 2 : 1;
                for (int qs = 0; qs < nq; qs++) {
#pragma unroll
                    for (int nt = 0; nt < 8; nt++)
                        mma_bf16(sf[nt], qf[qs][ks], Bf[nt][0], Bf[nt][1]);
                }
            }
        }

        // running max per row (quad-reduced) + shortlist append
        float tm0 = -1e30f, tm1 = -1e30f;
#pragma unroll
        for (int nt = 0; nt < 8; nt++) {
            tm0 = fmaxf(tm0, fmaxf(sf[nt][0], sf[nt][1]));
            tm1 = fmaxf(tm1, fmaxf(sf[nt][2], sf[nt][3]));
        }
        tm0 = fmaxf(tm0, __shfl_xor_sync(0xffffffffu, tm0, 1));
        tm0 = fmaxf(tm0, __shfl_xor_sync(0xffffffffu, tm0, 2));
        tm1 = fmaxf(tm1, __shfl_xor_sync(0xffffffffu, tm1, 1));
        tm1 = fmaxf(tm1, __shfl_xor_sync(0xffffffffu, tm1, 2));
        m0 = fmaxf(m0, tm0); m1 = fmaxf(m1, tm1);
        float th0 = m0 - (33.0f + fabsf(m0) * 1e-3f);
        float th1 = m1 - (33.0f + fabsf(m1) * 1e-3f);

#pragma unroll
        for (int nt = 0; nt < 8; nt++) {
#pragma unroll
            for (int j = 0; j < 4; j++) {
                float v = sf[nt][j];
                float th = (j >= 2) ? th1 : th0;
                int row = (j >= 2) ? r1loc : r0loc;
                if (v >= th) {
                    int key = kt * 64 + nt * 8 + cb + (j & 1);
                    int p = atomicAdd(&cnt[row], 1);
                    if (p < CAP) lists[row * CAP + p] = key;
                }
            }
        }
        __syncthreads();
    }
    __syncthreads();

    // ---- pass B: exact fp32 softmax over shortlist, thread-per-row ----
    if (tid < 128) {
        int row = tid, grow = q0 + row;
        int c = cnt[row];
        bool ovf = (c > CAP);
        if (c > CAP) c = CAP;
        int total = ovf ? Nn : c;

        float q[48];
        const float4* qp4 = (const float4*)(g_qkv + grow * 1152 + head * 48);
#pragma unroll
        for (int d4 = 0; d4 < 12; d4++) {
            float4 qv = qp4[d4];
            q[d4 * 4 + 0] = qv.x * qscale; q[d4 * 4 + 1] = qv.y * qscale;
            q[d4 * 4 + 2] = qv.z * qscale; q[d4 * 4 + 3] = qv.w * qscale;
        }

        float m = -1e30f, l = 0.f;
        float O[48];
#pragma unroll
        for (int d = 0; d < 48; d++) O[d] = 0.f;

        for (int i = 0; i < total; i++) {
            int key = ovf ? i : lists[row * CAP + i];
            const float4* kp4 = (const float4*)(g_qkv + key * 1152 + 384 + head * 48);
            float s = 0.f;
#pragma unroll
            for (int d4 = 0; d4 < 12; d4++) {
                float4 kv = kp4[d4];
                s += q[d4 * 4 + 0] * kv.x + q[d4 * 4 + 1] * kv.y
                   + q[d4 * 4 + 2] * kv.z + q[d4 * 4 + 3] * kv.w;
            }
            if (s > m) {
                float al = fexp2(m - s);
                l *= al;
#pragma unroll
                for (int d = 0; d < 48; d++) O[d] *= al;
                m = s;
            }
            float wgt = fexp2(s - m);
            l += wgt;
            const float4* vp4 = (const float4*)(g_qkv + key * 1152 + 768 + head * 48);
#pragma unroll
            for (int d4 = 0; d4 < 12; d4++) {
                float4 vv = vp4[d4];
                O[d4 * 4 + 0] += wgt * vv.x; O[d4 * 4 + 1] += wgt * vv.y;
                O[d4 * 4 + 2] += wgt * vv.z; O[d4 * 4 + 3] += wgt * vv.w;
            }
        }

        float inv = 1.f / l;
        int base = grow * 384 + head * 48;
#pragma unroll
        for (int d = 0; d < 48; d += 2)
            split3_pair(g_sC, base + d, O[d] * inv, O[d + 1] * inv);
    }
}

// ---------------- output projection + sigmoid --------------------------------
__global__ __launch_bounds__(256) void k_out(const float* __restrict__ Wout,
                                             const float* __restrict__ bout,
                                             float* __restrict__ out) {
    int warp = (blockIdx.x * blockDim.x + threadIdx.x) >> 5;
    int lane = threadIdx.x & 31;
    if (warp >= Nn) return;
    const float4* hr = (const float4*)(g_h + warp * Dd);
    const float4* wr = (const float4*)Wout;
    float s = 0.f;
#pragma unroll
    for (int q = 0; q < 3; q++) {
        float4 a = hr[lane + 32 * q];
        float4 b = wr[lane + 32 * q];
        s += a.x * b.x + a.y * b.y + a.z * b.z + a.w * b.w;
    }
#pragma unroll
    for (int off = 16; off; off >>= 1)
        s += __shfl_xor_sync(0xffffffffu, s, off);
    if (lane == 0) out[warp] = 1.f / (1.f + __expf(-(s + bout[0])));
}

// ---------------- launch ------------------------------------------------------
extern "C" void kernel_launch(void* const* d_in, const int* in_sizes, int n_in,
                              void* d_out, int out_size) {
    const float* emb  = (const float*)d_in[0];
    const int*   ei   = (const int*)d_in[1];
    const float* Wc   = (const float*)d_in[2];
    const float* bc   = (const float*)d_in[3];
    const float* Win  = (const float*)d_in[4];
    const float* bin  = (const float*)d_in[5];
    const float* Wao  = (const float*)d_in[6];
    const float* bao  = (const float*)d_in[7];
    const float* Wout = (const float*)d_in[8];
    const float* bout = (const float*)d_in[9];
    float* out = (float*)d_out;

    cudaFuncSetAttribute(k_flash_sel, cudaFuncAttributeMaxDynamicSharedMemorySize,
                         FL2_SMEM);
    cudaFuncSetAttribute(k_gemm_mma<0>, cudaFuncAttributeMaxDynamicSharedMemorySize,
                         GM_SMEM);
    cudaFuncSetAttribute(k_gemm_mma<1>, cudaFuncAttributeMaxDynamicSharedMemorySize,
                         GM_SMEM);
    cudaFuncSetAttribute(k_gemm_mma<2>, cudaFuncAttributeMaxDynamicSharedMemorySize,
                         GM_SMEM);

    // CSR build + weight splits (reused across all 3 layers)
    k_zero_deg<<<Nn / 256, 256>>>();
    k_hist<<<Ee / 256, 256>>>(ei);
    k_scan<<<1, 1024>>>();
    k_fill<<<Ee / 256, 256>>>(ei);
    k_copy<<<(Nn * Dd / 4) / 256, 256>>>(emb);
    k_wsplit<<<432, 256>>>(Wc, 0, 3 * Dd * Dd / 4);
    k_wsplit<<<432, 256>>>(Win, OFF_WIN, 3 * Dd * Dd / 4);
    k_wsplit<<<144, 256>>>(Wao, OFF_WAO, Dd * Dd / 4);

    for (int l = 0; l < Ll; l++) {
        k_gather<<<Nn / 8, 256>>>();
        k_gemm_mma<0><<<dim3(Dd / 64, Nn / 128), 256, GM_SMEM>>>(OFF_CONV(l),
                                                                 bc + l * Dd);
        k_gemm_mma<1><<<dim3(3 * Dd / 64, Nn / 128), 256, GM_SMEM>>>(OFF_WIN, bin);
        k_flash_sel<<<dim3(Nn / 128, Hh), 256, FL2_SMEM>>>();
        k_gemm_mma<2><<<dim3(Dd / 64, Nn / 128), 256, GM_SMEM>>>(OFF_WAO, bao);
    }
    k_out<<<Nn / 8, 256>>>(Wout, bout, out);
}

// round 15
// speedup vs baseline: 4.6486x; 4.6486x over previous
#include <cuda_runtime.h>
#include <cuda_bf16.h>
#include <math.h>
#include <stdint.h>

#define Nn 4096
#define Dd 384
#define Ee 131072
#define Hh 8
#define DHh 48
#define Ll 3
#define SEC (Hh * Nn * 48)

// ---------------- fast exp2 on the FMA pipe ----------------------------------
__device__ __forceinline__ float fexp2(float t) {
    t = fmaxf(t, -126.0f);
    float r = t + 12582912.0f;
    int n = __float_as_int(r) - 0x4B400000;
    float f = t - (r - 12582912.0f);
    float p = 1.8775767e-3f;
    p = fmaf(p, f, 8.9893397e-3f);
    p = fmaf(p, f, 5.5826318e-2f);
    p = fmaf(p, f, 2.4015361e-1f);
    p = fmaf(p, f, 6.9315308e-1f);
    p = fmaf(p, f, 1.0f);
    return __int_as_float(__float_as_int(p) + (n << 23));
}

// pack two fp32 -> bf16x2 word (low half = f0)
__device__ __forceinline__ uint32_t bf2(float f0, float f1) {
    uint32_t w;
    asm("cvt.rn.bf16x2.f32 %0, %1, %2;" : "=r"(w) : "f"(f1), "f"(f0));
    return w;
}
__device__ __forceinline__ float lof(uint32_t w) { return __uint_as_float(w << 16); }
__device__ __forceinline__ float hif(uint32_t w) { return __uint_as_float(w & 0xFFFF0000u); }

__device__ __forceinline__ uint32_t s2u(const void* p) {
    return (uint32_t)__cvta_generic_to_shared(p);
}
__device__ __forceinline__ void ldmx4(uint32_t r[4], uint32_t a) {
    asm volatile("ldmatrix.sync.aligned.m8n8.x4.shared.b16 {%0,%1,%2,%3}, [%4];"
                 : "=r"(r[0]), "=r"(r[1]), "=r"(r[2]), "=r"(r[3]) : "r"(a));
}
__device__ __forceinline__ void ldmx4t(uint32_t r[4], uint32_t a) {
    asm volatile("ldmatrix.sync.aligned.m8n8.x4.trans.shared.b16 {%0,%1,%2,%3}, [%4];"
                 : "=r"(r[0]), "=r"(r[1]), "=r"(r[2]), "=r"(r[3]) : "r"(a));
}
__device__ __forceinline__ void mma_bf16(float d[4], const uint32_t a[4],
                                         uint32_t b0, uint32_t b1) {
    asm volatile("mma.sync.aligned.m16n8k16.row.col.f32.bf16.bf16.f32 "
                 "{%0,%1,%2,%3}, {%4,%5,%6,%7}, {%8,%9}, {%0,%1,%2,%3};"
                 : "+f"(d[0]), "+f"(d[1]), "+f"(d[2]), "+f"(d[3])
                 : "r"(a[0]), "r"(a[1]), "r"(a[2]), "r"(a[3]), "r"(b0), "r"(b1));
}
__device__ __forceinline__ void cpasync16(uint32_t dst, const void* src) {
    asm volatile("cp.async.cg.shared.global [%0], [%1], 16;" :: "r"(dst), "l"(src));
}

// ---------------- scratch ----------------------------------------------------
__device__ __align__(16) float g_h[Nn * Dd];
__device__ int   g_deg[Nn];
__device__ float g_degf[Nn];
__device__ int   g_rowptr[Nn + 1];
__device__ int   g_fillpos[Nn];
__device__ int   g_colidx[Ee];
// bf16 split-3 activation buffers, layout [plane][node*384+col]
__device__ __align__(16) unsigned short g_sA[3][Nn * Dd];  // gather out (agg)
__device__ __align__(16) unsigned short g_sB[3][Nn * Dd];  // conv out  (hnew)
__device__ __align__(16) unsigned short g_sC[3][Nn * Dd];  // flash out (o)
// bf16 split-3 weights
#define WTOT 1032192
#define OFF_CONV(l) ((l) * Dd * Dd)
#define OFF_WIN (3 * Dd * Dd)
#define OFF_WAO (3 * Dd * Dd + 3 * Dd * Dd)
__device__ __align__(16) unsigned short g_ws[3][WTOT];
// flash-side Q/K/V split-2 tensors: [plane][head][node][48]
__device__ __align__(16) unsigned short g_qs[2 * SEC];   // Q hi/lo (scaled)
__device__ __align__(16) unsigned short g_kvs[4 * SEC];  // K hi/lo, V hi/lo

// split (v0,v1) into 3 bf16x2 planes of a [3][...] array
template <typename PT>
__device__ __forceinline__ void split3_pair(PT planes, int idx, float v0, float v1) {
    uint32_t w0 = bf2(v0, v1);
    *(uint32_t*)&planes[0][idx] = w0;
    float r0 = v0 - lof(w0), r1 = v1 - hif(w0);
    uint32_t w1 = bf2(r0, r1);
    *(uint32_t*)&planes[1][idx] = w1;
    *(uint32_t*)&planes[2][idx] = bf2(r0 - lof(w1), r1 - hif(w1));
}
__device__ __forceinline__ void split2s(unsigned short* base, int stride, int idx,
                                        float v0, float v1) {
    uint32_t w0 = bf2(v0, v1);
    *(uint32_t*)&base[idx] = w0;
    *(uint32_t*)&base[stride + idx] = bf2(v0 - lof(w0), v1 - hif(w0));
}

// ---------------- CSR build --------------------------------------------------
__global__ void k_zero_deg() {
    int i = blockIdx.x * blockDim.x + threadIdx.x;
    if (i < Nn) g_deg[i] = 0;
}
__global__ void k_hist(const int* __restrict__ ei) {
    int e = blockIdx.x * blockDim.x + threadIdx.x;
    if (e < Ee) atomicAdd(&g_deg[ei[e]], 1);
}
__global__ void k_scan() {
    __shared__ int s[1024];
    int tid = threadIdx.x;
    int b = tid * 4;
    int v0 = g_deg[b], v1 = g_deg[b + 1], v2 = g_deg[b + 2], v3 = g_deg[b + 3];
    int p1 = v0 + v1, p2 = p1 + v2, p3 = p2 + v3;
    s[tid] = p3;
    __syncthreads();
    for (int off = 1; off < 1024; off <<= 1) {
        int t = (tid >= off) ? s[tid - off] : 0;
        __syncthreads();
        if (tid >= off) s[tid] += t;
        __syncthreads();
    }
    int prev = tid ? s[tid - 1] : 0;
    int e0 = prev, e1 = prev + v0, e2 = prev + p1, e3 = prev + p2;
    g_rowptr[b] = e0; g_rowptr[b + 1] = e1; g_rowptr[b + 2] = e2; g_rowptr[b + 3] = e3;
    g_fillpos[b] = e0; g_fillpos[b + 1] = e1; g_fillpos[b + 2] = e2; g_fillpos[b + 3] = e3;
    g_degf[b] = (float)v0; g_degf[b + 1] = (float)v1;
    g_degf[b + 2] = (float)v2; g_degf[b + 3] = (float)v3;
    if (tid == 1023) g_rowptr[Nn] = s[1023];
}
__global__ void k_fill(const int* __restrict__ ei) {
    int e = blockIdx.x * blockDim.x + threadIdx.x;
    if (e < Ee) {
        int dst = ei[e];
        int src = ei[Ee + e];
        int pos = atomicAdd(&g_fillpos[dst], 1);
        g_colidx[pos] = src;
    }
}
__global__ void k_copy(const float* __restrict__ emb) {
    int i = blockIdx.x * blockDim.x + threadIdx.x;
    if (i < Nn * Dd / 4)
        ((float4*)g_h)[i] = ((const float4*)emb)[i];
}

// ---------------- weight split (once per launch) ------------------------------
__global__ __launch_bounds__(256) void k_wsplit(const float* __restrict__ src,
                                                int dstoff, int n4) {
    int i = blockIdx.x * 256 + threadIdx.x;
    if (i >= n4) return;
    float4 x = ((const float4*)src)[i];
    int idx = dstoff + i * 4;
    split3_pair(g_ws, idx, x.x, x.y);
    split3_pair(g_ws, idx + 2, x.z, x.w);
}

// ---------------- neighbor aggregation -> split-3 bf16 ------------------------
__global__ __launch_bounds__(256) void k_gather() {
    int warp = (blockIdx.x * blockDim.x + threadIdx.x) >> 5;
    int lane = threadIdx.x & 31;
    if (warp >= Nn) return;
    int pbeg = g_rowptr[warp], pend = g_rowptr[warp + 1];
    float4 a0 = {0, 0, 0, 0}, a1 = a0, a2 = a0;
    for (int p = pbeg; p < pend; p++) {
        int src = g_colidx[p];
        const float4* r = (const float4*)(g_h + src * Dd);
        float4 x;
        x = r[lane];      a0.x += x.x; a0.y += x.y; a0.z += x.z; a0.w += x.w;
        x = r[lane + 32]; a1.x += x.x; a1.y += x.y; a1.z += x.z; a1.w += x.w;
        x = r[lane + 64]; a2.x += x.x; a2.y += x.y; a2.z += x.z; a2.w += x.w;
    }
    int base = warp * Dd + lane * 4;
    split3_pair(g_sA, base, a0.x, a0.y);
    split3_pair(g_sA, base + 2, a0.z, a0.w);
    split3_pair(g_sA, base + 128, a1.x, a1.y);
    split3_pair(g_sA, base + 130, a1.z, a1.w);
    split3_pair(g_sA, base + 256, a2.x, a2.y);
    split3_pair(g_sA, base + 258, a2.z, a2.w);
}

// ---------------- pipelined mma.sync GEMM: C = A * B^T + epilogue -------------
// 32-col k-chunks, double-buffered via cp.async (2 x 36 KB). 64B smem rows,
// swizzle (ch ^ ((row>>1)&3))*16.
// MODE 0: A=g_sA -> split-3 g_sB, bias*degf               (conv)
// MODE 1: A=g_sB -> split-2 Q(scaled)/K/V into g_qs/g_kvs (qkv + fused split)
// MODE 2: A=g_sC -> fp32 g_h, bias+residual+relu          (attn out)
#define GM_BUF 36864
#define GM_SMEM 73728

template <int MODE>
__global__ __launch_bounds__(256, 2) void k_gemm_mma(int woff,
                                                     const float* __restrict__ bias) {
    extern __shared__ __align__(128) char sm[];
    uint32_t smb = s2u(sm);
    const int tid = threadIdx.x, lane = tid & 31, w = tid >> 5;
    const int row0 = blockIdx.y * 128, col0 = blockIdx.x * 64;
    const int l15 = lane & 15, l7 = lane & 7;
    const int lhi = lane >> 4, lmid = (lane >> 3) & 1;

    float of[8][4];
#pragma unroll
    for (int i = 0; i < 8; i++)
#pragma unroll
        for (int j = 0; j < 4; j++) of[i][j] = 0.f;

    auto stage = [&](int kc, int buf) {
        uint32_t bb = smb + buf * GM_BUF;
        for (int i = tid; i < 1536; i += 256) {
            int arr = i >> 9, rem = i & 511;
            int row = rem >> 2, ch = rem & 3;
            const unsigned short* ap = (MODE == 0) ? g_sA[arr]
                                     : (MODE == 1) ? g_sB[arr] : g_sC[arr];
            cpasync16(bb + arr * 8192 + row * 64 + ((ch ^ ((row >> 1) & 3)) * 16),
                      ap + (row0 + row) * 384 + kc * 32 + ch * 8);
        }
        for (int i = tid; i < 768; i += 256) {
            int arr = i >> 8, rem = i & 255;
            int n = rem >> 2, ch = rem & 3;
            cpasync16(bb + 24576 + arr * 4096 + n * 64 + ((ch ^ ((n >> 1) & 3)) * 16),
                      g_ws[arr] + woff + (col0 + n) * 384 + kc * 32 + ch * 8);
        }
        asm volatile("cp.async.commit_group;" ::: "memory");
    };

    stage(0, 0);
    for (int kc = 0; kc < 12; kc++) {
        int buf = kc & 1;
        if (kc + 1 < 12) stage(kc + 1, buf ^ 1);
        else asm volatile("cp.async.commit_group;" ::: "memory");
        asm volatile("cp.async.wait_group 1;" ::: "memory");
        __syncthreads();

        uint32_t bb = smb + buf * GM_BUF;
#pragma unroll
        for (int asp = 0; asp < 3; asp++) {
            uint32_t Af[2][4];
#pragma unroll
            for (int kst = 0; kst < 2; kst++) {
                int row = 16 * w + l15, ch = 2 * kst + lhi;
                ldmx4(Af[kst], bb + asp * 8192 + row * 64 +
                               ((ch ^ ((row >> 1) & 3)) * 16));
            }
#pragma unroll
            for (int bsp = 0; bsp < 3; bsp++) {
                if (bsp <= 2 - asp) {
#pragma unroll
                    for (int kst = 0; kst < 2; kst++) {
#pragma unroll
                        for (int np = 0; np < 4; np++) {
                            int key = 8 * (2 * np + lhi) + l7, ch = 2 * kst + lmid;
                            uint32_t r[4];
                            ldmx4(r, bb + 24576 + bsp * 4096 + key * 64 +
                                     ((ch ^ ((key >> 1) & 3)) * 16));
                            mma_bf16(of[2 * np], Af[kst], r[0], r[1]);
                            mma_bf16(of[2 * np + 1], Af[kst], r[2], r[3]);
                        }
                    }
                }
            }
        }
        __syncthreads();
    }

    // epilogue
    const float qscale = 0.14433756729740643f * 1.4426950408889634f;
    int r0 = row0 + 16 * w + (lane >> 2), r1 = r0 + 8;
    int cbl = (lane & 3) * 2;
    float dg0 = (MODE == 0) ? g_degf[r0] : 1.f;
    float dg1 = (MODE == 0) ? g_degf[r1] : 1.f;
#pragma unroll
    for (int nt = 0; nt < 8; nt++) {
        int n = col0 + nt * 8 + cbl;
        float b0 = bias[n], b1 = bias[n + 1];
        float v00 = of[nt][0] + b0 * dg0, v01 = of[nt][1] + b1 * dg0;
        float v10 = of[nt][2] + b0 * dg1, v11 = of[nt][3] + b1 * dg1;
        if (MODE == 0) {
            split3_pair(g_sB, r0 * 384 + n, v00, v01);
            split3_pair(g_sB, r1 * 384 + n, v10, v11);
        } else if (MODE == 1) {
            int sec = n / 384;
            int wn = n - sec * 384;
            int hd = wn / 48, d = wn - hd * 48;
            int i0 = (hd * Nn + r0) * 48 + d;
            int i1 = (hd * Nn + r1) * 48 + d;
            if (sec == 0) {
                split2s(g_qs, SEC, i0, v00 * qscale, v01 * qscale);
                split2s(g_qs, SEC, i1, v10 * qscale, v11 * qscale);
            } else if (sec == 1) {
                split2s(g_kvs, SEC, i0, v00, v01);
                split2s(g_kvs, SEC, i1, v10, v11);
            } else {
                split2s(g_kvs + 2 * SEC, SEC, i0, v00, v01);
                split2s(g_kvs + 2 * SEC, SEC, i1, v10, v11);
            }
        } else {
            float2 h0 = *(const float2*)&g_h[r0 * 384 + n];
            float2 h1 = *(const float2*)&g_h[r1 * 384 + n];
            *(float2*)&g_h[r0 * 384 + n] =
                make_float2(fmaxf(v00 + h0.x, 0.f), fmaxf(v01 + h0.y, 0.f));
            *(float2*)&g_h[r1 * 384 + n] =
                make_float2(fmaxf(v10 + h1.x, 0.f), fmaxf(v11 + h1.y, 0.f));
        }
    }
}

// ---------------- mma.sync flash attention (pipelined, 3-term S) --------------
// Q A-fragments in registers (split-2); K split-2, V split-2 double-buffered via
// cp.async. smem = 2 x 32768 B (K 2x8KB + V 2x8KB per buffer).
// S terms {00,01,10}: error ~|S|*2^-16 -> softmax weight err ~0.1-0.35%.
#define FL_BUF 32768
#define FL_SMEM 65536

__device__ __forceinline__ void flash_stage(uint32_t smb, int hN, int k0,
                                            int buf, int tid) {
    for (int i = tid; i < 1536; i += 256) {
        int arr = i / 384, rem = i - arr * 384;   // arr: 0,1=K hi/lo; 2,3=V hi/lo
        int row = rem / 6, c = rem - row * 6;
        const unsigned short* src = g_kvs + arr * SEC + (hN + k0 + row) * 48 + c * 8;
        uint32_t dst = smb + buf * FL_BUF + arr * 8192 + row * 128 +
                       ((c * 16) ^ ((row & 7) * 16));
        cpasync16(dst, src);
    }
    asm volatile("cp.async.commit_group;" ::: "memory");
}

__global__ __launch_bounds__(256, 2) void k_flash_mma() {
    extern __shared__ __align__(128) char sm[];
    uint32_t smb = s2u(sm);
    const int tid = threadIdx.x, lane = tid & 31, w = tid >> 5;
    const int head = blockIdx.y, q0 = blockIdx.x * 128;
    const int hN = head * Nn;
    const int l15 = lane & 15, l7 = lane & 7;
    const int lhi = lane >> 4, lmid = (lane >> 3) & 1;

    // Q A-fragments direct from global (row=16w+g(+8), col=16ks+2t(+8))
    uint32_t qf[2][3][4];
    {
        int rl = 16 * w + (lane >> 2);
        int cq = (lane & 3) * 2;
#pragma unroll
        for (int qs = 0; qs < 2; qs++) {
            const unsigned short* qp = g_qs + qs * SEC + (hN + q0) * 48;
#pragma unroll
            for (int ks = 0; ks < 3; ks++) {
                int c = 16 * ks + cq;
                qf[qs][ks][0] = *(const uint32_t*)&qp[rl * 48 + c];
                qf[qs][ks][1] = *(const uint32_t*)&qp[(rl + 8) * 48 + c];
                qf[qs][ks][2] = *(const uint32_t*)&qp[rl * 48 + c + 8];
                qf[qs][ks][3] = *(const uint32_t*)&qp[(rl + 8) * 48 + c + 8];
            }
        }
    }

    float of[6][4];
#pragma unroll
    for (int n = 0; n < 6; n++)
#pragma unroll
        for (int j = 0; j < 4; j++) of[n][j] = 0.f;
    float mr0 = -1e30f, mr1 = -1e30f, lr0 = 0.f, lr1 = 0.f;

    flash_stage(smb, hN, 0, 0, tid);   // prologue: tile 0 in flight

    for (int kt = 0; kt < 64; kt++) {
        int buf = kt & 1;
        uint32_t kvb = smb + buf * FL_BUF;
        if (kt + 1 < 64)
            flash_stage(smb, hN, (kt + 1) * 64, buf ^ 1, tid);
        else
            asm volatile("cp.async.commit_group;" ::: "memory");
        asm volatile("cp.async.wait_group 1;" ::: "memory");
        __syncthreads();

        // ---- S = 3 bf16 split terms {00,01,10} ----
        float sf[8][4];
#pragma unroll
        for (int nt = 0; nt < 8; nt++)
#pragma unroll
            for (int j = 0; j < 4; j++) sf[nt][j] = 0.f;

#pragma unroll
        for (int ks = 0; ks < 3; ks++) {
#pragma unroll
            for (int kk = 0; kk < 2; kk++) {
                uint32_t Bf[8][2];
#pragma unroll
                for (int np = 0; np < 4; np++) {
                    int key = 8 * (2 * np + lhi) + l7;
                    int ch = 2 * ks + lmid;
                    uint32_t r[4];
                    ldmx4(r, kvb + kk * 8192 + key * 128 +
                             ((ch * 16) ^ ((key & 7) * 16)));
                    Bf[2 * np][0] = r[0]; Bf[2 * np][1] = r[1];
                    Bf[2 * np + 1][0] = r[2]; Bf[2 * np + 1][1] = r[3];
                }
                int nq = (kk == 0) ? 2 : 1;   // terms {00,10} and {01}
                for (int qs = 0; qs < nq; qs++) {
#pragma unroll
                    for (int nt = 0; nt < 8; nt++)
                        mma_bf16(sf[nt], qf[qs][ks], Bf[nt][0], Bf[nt][1]);
                }
            }
        }

        // ---- online softmax (base-2) ----
        float vmax0 = -1e30f, vmax1 = -1e30f;
#pragma unroll
        for (int nt = 0; nt < 8; nt++) {
            vmax0 = fmaxf(vmax0, fmaxf(sf[nt][0], sf[nt][1]));
            vmax1 = fmaxf(vmax1, fmaxf(sf[nt][2], sf[nt][3]));
        }
        vmax0 = fmaxf(vmax0, __shfl_xor_sync(0xffffffffu, vmax0, 1));
        vmax0 = fmaxf(vmax0, __shfl_xor_sync(0xffffffffu, vmax0, 2));
        vmax1 = fmaxf(vmax1, __shfl_xor_sync(0xffffffffu, vmax1, 1));
        vmax1 = fmaxf(vmax1, __shfl_xor_sync(0xffffffffu, vmax1, 2));
        float nm0 = fmaxf(mr0, vmax0), nm1 = fmaxf(mr1, vmax1);
        float al0 = fexp2(mr0 - nm0), al1 = fexp2(mr1 - nm1);
        mr0 = nm0; mr1 = nm1;

        uint32_t pA[4][4];
        float ps0 = 0.f, ps1 = 0.f;
#pragma unroll
        for (int t = 0; t < 4; t++) {
            float p00 = fexp2(sf[2 * t][0] - nm0), p01 = fexp2(sf[2 * t][1] - nm0);
            float p10 = fexp2(sf[2 * t][2] - nm1), p11 = fexp2(sf[2 * t][3] - nm1);
            float p20 = fexp2(sf[2 * t + 1][0] - nm0), p21 = fexp2(sf[2 * t + 1][1] - nm0);
            float p30 = fexp2(sf[2 * t + 1][2] - nm1), p31 = fexp2(sf[2 * t + 1][3] - nm1);
            uint32_t w0 = bf2(p00, p01), w1 = bf2(p10, p11);
            uint32_t w2 = bf2(p20, p21), w3 = bf2(p30, p31);
            pA[t][0] = w0; pA[t][1] = w1; pA[t][2] = w2; pA[t][3] = w3;
            ps0 += lof(w0) + hif(w0) + lof(w2) + hif(w2);
            ps1 += lof(w1) + hif(w1) + lof(w3) + hif(w3);
        }
        ps0 += __shfl_xor_sync(0xffffffffu, ps0, 1);
        ps0 += __shfl_xor_sync(0xffffffffu, ps0, 2);
        ps1 += __shfl_xor_sync(0xffffffffu, ps1, 1);
        ps1 += __shfl_xor_sync(0xffffffffu, ps1, 2);
        lr0 = lr0 * al0 + ps0;
        lr1 = lr1 * al1 + ps1;
#pragma unroll
        for (int n = 0; n < 6; n++) {
            of[n][0] *= al0; of[n][1] *= al0;
            of[n][2] *= al1; of[n][3] *= al1;
        }

        // ---- O += P V (V split-2 at kvb+16384) ----
#pragma unroll
        for (int t = 0; t < 4; t++) {
#pragma unroll
            for (int vs = 0; vs < 2; vs++) {
#pragma unroll
                for (int np = 0; np < 3; np++) {
                    int key = 16 * t + l15;
                    int ch = 2 * np + lhi;
                    uint32_t r[4];
                    ldmx4t(r, kvb + 16384 + vs * 8192 + key * 128 +
                              ((ch * 16) ^ ((key & 7) * 16)));
                    mma_bf16(of[2 * np], pA[t], r[0], r[1]);
                    mma_bf16(of[2 * np + 1], pA[t], r[2], r[3]);
                }
            }
        }
        __syncthreads();
    }

    // ---- epilogue: normalize + split-3 store to g_sC ----
    float inv0 = 1.f / lr0, inv1 = 1.f / lr1;
    int r0 = q0 + 16 * w + (lane >> 2), r1 = r0 + 8;
    int cb = head * 48 + (lane & 3) * 2;
#pragma unroll
    for (int n = 0; n < 6; n++) {
        split3_pair(g_sC, r0 * 384 + cb + n * 8, of[n][0] * inv0, of[n][1] * inv0);
        split3_pair(g_sC, r1 * 384 + cb + n * 8, of[n][2] * inv1, of[n][3] * inv1);
    }
}

// ---------------- output projection + sigmoid --------------------------------
__global__ __launch_bounds__(256) void k_out(const float* __restrict__ Wout,
                                             const float* __restrict__ bout,
                                             float* __restrict__ out) {
    int warp = (blockIdx.x * blockDim.x + threadIdx.x) >> 5;
    int lane = threadIdx.x & 31;
    if (warp >= Nn) return;
    const float4* hr = (const float4*)(g_h + warp * Dd);
    const float4* wr = (const float4*)Wout;
    float s = 0.f;
#pragma unroll
    for (int q = 0; q < 3; q++) {
        float4 a = hr[lane + 32 * q];
        float4 b = wr[lane + 32 * q];
        s += a.x * b.x + a.y * b.y + a.z * b.z + a.w * b.w;
    }
#pragma unroll
    for (int off = 16; off; off >>= 1)
        s += __shfl_xor_sync(0xffffffffu, s, off);
    if (lane == 0) out[warp] = 1.f / (1.f + __expf(-(s + bout[0])));
}

// ---------------- launch ------------------------------------------------------
extern "C" void kernel_launch(void* const* d_in, const int* in_sizes, int n_in,
                              void* d_out, int out_size) {
    const float* emb  = (const float*)d_in[0];
    const int*   ei   = (const int*)d_in[1];
    const float* Wc   = (const float*)d_in[2];
    const float* bc   = (const float*)d_in[3];
    const float* Win  = (const float*)d_in[4];
    const float* bin  = (const float*)d_in[5];
    const float* Wao  = (const float*)d_in[6];
    const float* bao  = (const float*)d_in[7];
    const float* Wout = (const float*)d_in[8];
    const float* bout = (const float*)d_in[9];
    float* out = (float*)d_out;

    cudaFuncSetAttribute(k_flash_mma, cudaFuncAttributeMaxDynamicSharedMemorySize,
                         FL_SMEM);
    cudaFuncSetAttribute(k_gemm_mma<0>, cudaFuncAttributeMaxDynamicSharedMemorySize,
                         GM_SMEM);
    cudaFuncSetAttribute(k_gemm_mma<1>, cudaFuncAttributeMaxDynamicSharedMemorySize,
                         GM_SMEM);
    cudaFuncSetAttribute(k_gemm_mma<2>, cudaFuncAttributeMaxDynamicSharedMemorySize,
                         GM_SMEM);

    // CSR build + weight splits (reused across all 3 layers)
    k_zero_deg<<<Nn / 256, 256>>>();
    k_hist<<<Ee / 256, 256>>>(ei);
    k_scan<<<1, 1024>>>();
    k_fill<<<Ee / 256, 256>>>(ei);
    k_copy<<<(Nn * Dd / 4) / 256, 256>>>(emb);
    k_wsplit<<<432, 256>>>(Wc, 0, 3 * Dd * Dd / 4);
    k_wsplit<<<432, 256>>>(Win, OFF_WIN, 3 * Dd * Dd / 4);
    k_wsplit<<<144, 256>>>(Wao, OFF_WAO, Dd * Dd / 4);

    for (int l = 0; l < Ll; l++) {
        k_gather<<<Nn / 8, 256>>>();
        k_gemm_mma<0><<<dim3(Dd / 64, Nn / 128), 256, GM_SMEM>>>(OFF_CONV(l),
                                                                 bc + l * Dd);
        k_gemm_mma<1><<<dim3(3 * Dd / 64, Nn / 128), 256, GM_SMEM>>>(OFF_WIN, bin);
        k_flash_mma<<<dim3(Nn / 128, Hh), 256, FL_SMEM>>>();
        k_gemm_mma<2><<<dim3(Dd / 64, Nn / 128), 256, GM_SMEM>>>(OFF_WAO, bao);
    }
    k_out<<<Nn / 8, 256>>>(Wout, bout, out);
}

// round 16
// speedup vs baseline: 5.3354x; 1.1477x over previous
#include <cuda_runtime.h>
#include <cuda_bf16.h>
#include <math.h>
#include <stdint.h>

#define Nn 4096
#define Dd 384
#define Ee 131072
#define Hh 8
#define DHh 48
#define Ll 3
#define SEC (Hh * Nn * 48)

// ---------------- fast exp2 on the FMA pipe ----------------------------------
__device__ __forceinline__ float fexp2(float t) {
    t = fmaxf(t, -126.0f);
    float r = t + 12582912.0f;
    int n = __float_as_int(r) - 0x4B400000;
    float f = t - (r - 12582912.0f);
    float p = 1.8775767e-3f;
    p = fmaf(p, f, 8.9893397e-3f);
    p = fmaf(p, f, 5.5826318e-2f);
    p = fmaf(p, f, 2.4015361e-1f);
    p = fmaf(p, f, 6.9315308e-1f);
    p = fmaf(p, f, 1.0f);
    return __int_as_float(__float_as_int(p) + (n << 23));
}

// pack two fp32 -> bf16x2 word (low half = f0)
__device__ __forceinline__ uint32_t bf2(float f0, float f1) {
    uint32_t w;
    asm("cvt.rn.bf16x2.f32 %0, %1, %2;" : "=r"(w) : "f"(f1), "f"(f0));
    return w;
}
__device__ __forceinline__ float lof(uint32_t w) { return __uint_as_float(w << 16); }
__device__ __forceinline__ float hif(uint32_t w) { return __uint_as_float(w & 0xFFFF0000u); }

__device__ __forceinline__ uint32_t s2u(const void* p) {
    return (uint32_t)__cvta_generic_to_shared(p);
}
__device__ __forceinline__ void ldmx4(uint32_t r[4], uint32_t a) {
    asm volatile("ldmatrix.sync.aligned.m8n8.x4.shared.b16 {%0,%1,%2,%3}, [%4];"
                 : "=r"(r[0]), "=r"(r[1]), "=r"(r[2]), "=r"(r[3]) : "r"(a));
}
__device__ __forceinline__ void ldmx4t(uint32_t r[4], uint32_t a) {
    asm volatile("ldmatrix.sync.aligned.m8n8.x4.trans.shared.b16 {%0,%1,%2,%3}, [%4];"
                 : "=r"(r[0]), "=r"(r[1]), "=r"(r[2]), "=r"(r[3]) : "r"(a));
}
__device__ __forceinline__ void mma_bf16(float d[4], const uint32_t a[4],
                                         uint32_t b0, uint32_t b1) {
    asm volatile("mma.sync.aligned.m16n8k16.row.col.f32.bf16.bf16.f32 "
                 "{%0,%1,%2,%3}, {%4,%5,%6,%7}, {%8,%9}, {%0,%1,%2,%3};"
                 : "+f"(d[0]), "+f"(d[1]), "+f"(d[2]), "+f"(d[3])
                 : "r"(a[0]), "r"(a[1]), "r"(a[2]), "r"(a[3]), "r"(b0), "r"(b1));
}
__device__ __forceinline__ void cpasync16(uint32_t dst, const void* src) {
    asm volatile("cp.async.cg.shared.global [%0], [%1], 16;" :: "r"(dst), "l"(src));
}

// ---------------- scratch ----------------------------------------------------
__device__ __align__(16) float g_h[Nn * Dd];
__device__ int   g_deg[Nn];
__device__ float g_degf[Nn];
__device__ int   g_rowptr[Nn + 1];
__device__ int   g_fillpos[Nn];
__device__ int   g_colidx[Ee];
// bf16 split-2 activation buffers, layout [plane][node*384+col]
__device__ __align__(16) unsigned short g_sA[2][Nn * Dd];  // gather out (agg)
__device__ __align__(16) unsigned short g_sB[2][Nn * Dd];  // conv out  (hnew)
__device__ __align__(16) unsigned short g_sC[2][Nn * Dd];  // flash out (o)
// bf16 split-2 weights
#define WTOT 1032192
#define OFF_CONV(l) ((l) * Dd * Dd)
#define OFF_WIN (3 * Dd * Dd)
#define OFF_WAO (3 * Dd * Dd + 3 * Dd * Dd)
__device__ __align__(16) unsigned short g_ws[2][WTOT];
// flash-side Q/K/V split-2 tensors: [plane][head][node][48]
__device__ __align__(16) unsigned short g_qs[2 * SEC];   // Q hi/lo (scaled)
__device__ __align__(16) unsigned short g_kvs[4 * SEC];  // K hi/lo, V hi/lo

// split (v0,v1) into 2 bf16x2 planes of a [2][...] array
template <typename PT>
__device__ __forceinline__ void split2_pair(PT planes, int idx, float v0, float v1) {
    uint32_t w0 = bf2(v0, v1);
    *(uint32_t*)&planes[0][idx] = w0;
    *(uint32_t*)&planes[1][idx] = bf2(v0 - lof(w0), v1 - hif(w0));
}
__device__ __forceinline__ void split2s(unsigned short* base, int stride, int idx,
                                        float v0, float v1) {
    uint32_t w0 = bf2(v0, v1);
    *(uint32_t*)&base[idx] = w0;
    *(uint32_t*)&base[stride + idx] = bf2(v0 - lof(w0), v1 - hif(w0));
}

// ---------------- CSR build --------------------------------------------------
__global__ void k_zero_deg() {
    int i = blockIdx.x * blockDim.x + threadIdx.x;
    if (i < Nn) g_deg[i] = 0;
}
__global__ void k_hist(const int* __restrict__ ei) {
    int e = blockIdx.x * blockDim.x + threadIdx.x;
    if (e < Ee) atomicAdd(&g_deg[ei[e]], 1);
}
__global__ void k_scan() {
    __shared__ int s[1024];
    int tid = threadIdx.x;
    int b = tid * 4;
    int v0 = g_deg[b], v1 = g_deg[b + 1], v2 = g_deg[b + 2], v3 = g_deg[b + 3];
    int p1 = v0 + v1, p2 = p1 + v2, p3 = p2 + v3;
    s[tid] = p3;
    __syncthreads();
    for (int off = 1; off < 1024; off <<= 1) {
        int t = (tid >= off) ? s[tid - off] : 0;
        __syncthreads();
        if (tid >= off) s[tid] += t;
        __syncthreads();
    }
    int prev = tid ? s[tid - 1] : 0;
    int e0 = prev, e1 = prev + v0, e2 = prev + p1, e3 = prev + p2;
    g_rowptr[b] = e0; g_rowptr[b + 1] = e1; g_rowptr[b + 2] = e2; g_rowptr[b + 3] = e3;
    g_fillpos[b] = e0; g_fillpos[b + 1] = e1; g_fillpos[b + 2] = e2; g_fillpos[b + 3] = e3;
    g_degf[b] = (float)v0; g_degf[b + 1] = (float)v1;
    g_degf[b + 2] = (float)v2; g_degf[b + 3] = (float)v3;
    if (tid == 1023) g_rowptr[Nn] = s[1023];
}
__global__ void k_fill(const int* __restrict__ ei) {
    int e = blockIdx.x * blockDim.x + threadIdx.x;
    if (e < Ee) {
        int dst = ei[e];
        int src = ei[Ee + e];
        int pos = atomicAdd(&g_fillpos[dst], 1);
        g_colidx[pos] = src;
    }
}
__global__ void k_copy(const float* __restrict__ emb) {
    int i = blockIdx.x * blockDim.x + threadIdx.x;
    if (i < Nn * Dd / 4)
        ((float4*)g_h)[i] = ((const float4*)emb)[i];
}

// ---------------- weight split (once per launch) ------------------------------
__global__ __launch_bounds__(256) void k_wsplit(const float* __restrict__ src,
                                                int dstoff, int n4) {
    int i = blockIdx.x * 256 + threadIdx.x;
    if (i >= n4) return;
    float4 x = ((const float4*)src)[i];
    int idx = dstoff + i * 4;
    split2_pair(g_ws, idx, x.x, x.y);
    split2_pair(g_ws, idx + 2, x.z, x.w);
}

// ---------------- neighbor aggregation -> split-2 bf16 ------------------------
__global__ __launch_bounds__(256) void k_gather() {
    int warp = (blockIdx.x * blockDim.x + threadIdx.x) >> 5;
    int lane = threadIdx.x & 31;
    if (warp >= Nn) return;
    int pbeg = g_rowptr[warp], pend = g_rowptr[warp + 1];
    float4 a0 = {0, 0, 0, 0}, a1 = a0, a2 = a0;
    for (int p = pbeg; p < pend; p++) {
        int src = g_colidx[p];
        const float4* r = (const float4*)(g_h + src * Dd);
        float4 x;
        x = r[lane];      a0.x += x.x; a0.y += x.y; a0.z += x.z; a0.w += x.w;
        x = r[lane + 32]; a1.x += x.x; a1.y += x.y; a1.z += x.z; a1.w += x.w;
        x = r[lane + 64]; a2.x += x.x; a2.y += x.y; a2.z += x.z; a2.w += x.w;
    }
    int base = warp * Dd + lane * 4;
    split2_pair(g_sA, base, a0.x, a0.y);
    split2_pair(g_sA, base + 2, a0.z, a0.w);
    split2_pair(g_sA, base + 128, a1.x, a1.y);
    split2_pair(g_sA, base + 130, a1.z, a1.w);
    split2_pair(g_sA, base + 256, a2.x, a2.y);
    split2_pair(g_sA, base + 258, a2.z, a2.w);
}

// ---------------- pipelined mma.sync GEMM: C = A * B^T + epilogue -------------
// 32-col k-chunks, double-buffered via cp.async (2 x 24 KB). 64B smem rows,
// swizzle (ch ^ ((row>>1)&3))*16. 3 terms {00,01,10}, split-2 operands.
// MODE 0: A=g_sA -> split-2 g_sB, bias*degf               (conv)
// MODE 1: A=g_sB -> split-2 Q(scaled)/K/V into g_qs/g_kvs (qkv + fused split)
// MODE 2: A=g_sC -> fp32 g_h, bias+residual+relu          (attn out)
#define GM_BUF 24576
#define GM_SMEM 49152

template <int MODE>
__global__ __launch_bounds__(256, 2) void k_gemm_mma(int woff,
                                                     const float* __restrict__ bias) {
    extern __shared__ __align__(128) char sm[];
    uint32_t smb = s2u(sm);
    const int tid = threadIdx.x, lane = tid & 31, w = tid >> 5;
    const int row0 = blockIdx.y * 128, col0 = blockIdx.x * 64;
    const int l15 = lane & 15, l7 = lane & 7;
    const int lhi = lane >> 4, lmid = (lane >> 3) & 1;

    float of[8][4];
#pragma unroll
    for (int i = 0; i < 8; i++)
#pragma unroll
        for (int j = 0; j < 4; j++) of[i][j] = 0.f;

    auto stage = [&](int kc, int buf) {
        uint32_t bb = smb + buf * GM_BUF;
        // A: 2 planes x 128 rows x 4 chunks(16B)
        for (int i = tid; i < 1024; i += 256) {
            int arr = i >> 9, rem = i & 511;
            int row = rem >> 2, ch = rem & 3;
            const unsigned short* ap = (MODE == 0) ? g_sA[arr]
                                     : (MODE == 1) ? g_sB[arr] : g_sC[arr];
            cpasync16(bb + arr * 8192 + row * 64 + ((ch ^ ((row >> 1) & 3)) * 16),
                      ap + (row0 + row) * 384 + kc * 32 + ch * 8);
        }
        // B: 2 planes x 64 rows x 4 chunks
        for (int i = tid; i < 512; i += 256) {
            int arr = i >> 8, rem = i & 255;
            int n = rem >> 2, ch = rem & 3;
            cpasync16(bb + 16384 + arr * 4096 + n * 64 + ((ch ^ ((n >> 1) & 3)) * 16),
                      g_ws[arr] + woff + (col0 + n) * 384 + kc * 32 + ch * 8);
        }
        asm volatile("cp.async.commit_group;" ::: "memory");
    };

    stage(0, 0);
    for (int kc = 0; kc < 12; kc++) {
        int buf = kc & 1;
        if (kc + 1 < 12) stage(kc + 1, buf ^ 1);
        else asm volatile("cp.async.commit_group;" ::: "memory");
        asm volatile("cp.async.wait_group 1;" ::: "memory");
        __syncthreads();

        uint32_t bb = smb + buf * GM_BUF;
#pragma unroll
        for (int asp = 0; asp < 2; asp++) {
            uint32_t Af[2][4];
#pragma unroll
            for (int kst = 0; kst < 2; kst++) {
                int row = 16 * w + l15, ch = 2 * kst + lhi;
                ldmx4(Af[kst], bb + asp * 8192 + row * 64 +
                               ((ch ^ ((row >> 1) & 3)) * 16));
            }
#pragma unroll
            for (int bsp = 0; bsp < 2; bsp++) {
                if (asp + bsp <= 1) {
#pragma unroll
                    for (int kst = 0; kst < 2; kst++) {
#pragma unroll
                        for (int np = 0; np < 4; np++) {
                            int key = 8 * (2 * np + lhi) + l7, ch = 2 * kst + lmid;
                            uint32_t r[4];
                            ldmx4(r, bb + 16384 + bsp * 4096 + key * 64 +
                                     ((ch ^ ((key >> 1) & 3)) * 16));
                            mma_bf16(of[2 * np], Af[kst], r[0], r[1]);
                            mma_bf16(of[2 * np + 1], Af[kst], r[2], r[3]);
                        }
                    }
                }
            }
        }
        __syncthreads();
    }

    // epilogue
    const float qscale = 0.14433756729740643f * 1.4426950408889634f;
    int r0 = row0 + 16 * w + (lane >> 2), r1 = r0 + 8;
    int cbl = (lane & 3) * 2;
    float dg0 = (MODE == 0) ? g_degf[r0] : 1.f;
    float dg1 = (MODE == 0) ? g_degf[r1] : 1.f;
#pragma unroll
    for (int nt = 0; nt < 8; nt++) {
        int n = col0 + nt * 8 + cbl;
        float b0 = bias[n], b1 = bias[n + 1];
        float v00 = of[nt][0] + b0 * dg0, v01 = of[nt][1] + b1 * dg0;
        float v10 = of[nt][2] + b0 * dg1, v11 = of[nt][3] + b1 * dg1;
        if (MODE == 0) {
            split2_pair(g_sB, r0 * 384 + n, v00, v01);
            split2_pair(g_sB, r1 * 384 + n, v10, v11);
        } else if (MODE == 1) {
            int sec = n / 384;
            int wn = n - sec * 384;
            int hd = wn / 48, d = wn - hd * 48;
            int i0 = (hd * Nn + r0) * 48 + d;
            int i1 = (hd * Nn + r1) * 48 + d;
            if (sec == 0) {
                split2s(g_qs, SEC, i0, v00 * qscale, v01 * qscale);
                split2s(g_qs, SEC, i1, v10 * qscale, v11 * qscale);
            } else if (sec == 1) {
                split2s(g_kvs, SEC, i0, v00, v01);
                split2s(g_kvs, SEC, i1, v10, v11);
            } else {
                split2s(g_kvs + 2 * SEC, SEC, i0, v00, v01);
                split2s(g_kvs + 2 * SEC, SEC, i1, v10, v11);
            }
        } else {
            float2 h0 = *(const float2*)&g_h[r0 * 384 + n];
            float2 h1 = *(const float2*)&g_h[r1 * 384 + n];
            *(float2*)&g_h[r0 * 384 + n] =
                make_float2(fmaxf(v00 + h0.x, 0.f), fmaxf(v01 + h0.y, 0.f));
            *(float2*)&g_h[r1 * 384 + n] =
                make_float2(fmaxf(v10 + h1.x, 0.f), fmaxf(v11 + h1.y, 0.f));
        }
    }
}

// ---------------- mma.sync flash attention (pipelined, 3-term S) --------------
// Q A-fragments in registers (split-2); K split-2, V split-2 double-buffered via
// cp.async. smem = 2 x 32768 B (K 2x8KB + V 2x8KB per buffer).
#define FL_BUF 32768
#define FL_SMEM 65536

__device__ __forceinline__ void flash_stage(uint32_t smb, int hN, int k0,
                                            int buf, int tid) {
    for (int i = tid; i < 1536; i += 256) {
        int arr = i / 384, rem = i - arr * 384;   // arr: 0,1=K hi/lo; 2,3=V hi/lo
        int row = rem / 6, c = rem - row * 6;
        const unsigned short* src = g_kvs + arr * SEC + (hN + k0 + row) * 48 + c * 8;
        uint32_t dst = smb + buf * FL_BUF + arr * 8192 + row * 128 +
                       ((c * 16) ^ ((row & 7) * 16));
        cpasync16(dst, src);
    }
    asm volatile("cp.async.commit_group;" ::: "memory");
}

__global__ __launch_bounds__(256, 2) void k_flash_mma() {
    extern __shared__ __align__(128) char sm[];
    uint32_t smb = s2u(sm);
    const int tid = threadIdx.x, lane = tid & 31, w = tid >> 5;
    const int head = blockIdx.y, q0 = blockIdx.x * 128;
    const int hN = head * Nn;
    const int l15 = lane & 15, l7 = lane & 7;
    const int lhi = lane >> 4, lmid = (lane >> 3) & 1;

    // Q A-fragments direct from global (row=16w+g(+8), col=16ks+2t(+8))
    uint32_t qf[2][3][4];
    {
        int rl = 16 * w + (lane >> 2);
        int cq = (lane & 3) * 2;
#pragma unroll
        for (int qs = 0; qs < 2; qs++) {
            const unsigned short* qp = g_qs + qs * SEC + (hN + q0) * 48;
#pragma unroll
            for (int ks = 0; ks < 3; ks++) {
                int c = 16 * ks + cq;
                qf[qs][ks][0] = *(const uint32_t*)&qp[rl * 48 + c];
                qf[qs][ks][1] = *(const uint32_t*)&qp[(rl + 8) * 48 + c];
                qf[qs][ks][2] = *(const uint32_t*)&qp[rl * 48 + c + 8];
                qf[qs][ks][3] = *(const uint32_t*)&qp[(rl + 8) * 48 + c + 8];
            }
        }
    }

    float of[6][4];
#pragma unroll
    for (int n = 0; n < 6; n++)
#pragma unroll
        for (int j = 0; j < 4; j++) of[n][j] = 0.f;
    float mr0 = -1e30f, mr1 = -1e30f, lr0 = 0.f, lr1 = 0.f;

    flash_stage(smb, hN, 0, 0, tid);   // prologue: tile 0 in flight

    for (int kt = 0; kt < 64; kt++) {
        int buf = kt & 1;
        uint32_t kvb = smb + buf * FL_BUF;
        if (kt + 1 < 64)
            flash_stage(smb, hN, (kt + 1) * 64, buf ^ 1, tid);
        else
            asm volatile("cp.async.commit_group;" ::: "memory");
        asm volatile("cp.async.wait_group 1;" ::: "memory");
        __syncthreads();

        // ---- S = 3 bf16 split terms {00,01,10} ----
        float sf[8][4];
#pragma unroll
        for (int nt = 0; nt < 8; nt++)
#pragma unroll
            for (int j = 0; j < 4; j++) sf[nt][j] = 0.f;

#pragma unroll
        for (int ks = 0; ks < 3; ks++) {
#pragma unroll
            for (int kk = 0; kk < 2; kk++) {
                uint32_t Bf[8][2];
#pragma unroll
                for (int np = 0; np < 4; np++) {
                    int key = 8 * (2 * np + lhi) + l7;
                    int ch = 2 * ks + lmid;
                    uint32_t r[4];
                    ldmx4(r, kvb + kk * 8192 + key * 128 +
                             ((ch * 16) ^ ((key & 7) * 16)));
                    Bf[2 * np][0] = r[0]; Bf[2 * np][1] = r[1];
                    Bf[2 * np + 1][0] = r[2]; Bf[2 * np + 1][1] = r[3];
                }
                int nq = (kk == 0) ? 2 : 1;   // terms {00,10} and {01}
                for (int qs = 0; qs < nq; qs++) {
#pragma unroll
                    for (int nt = 0; nt < 8; nt++)
                        mma_bf16(sf[nt], qf[qs][ks], Bf[nt][0], Bf[nt][1]);
                }
            }
        }

        // ---- online softmax (base-2) ----
        float vmax0 = -1e30f, vmax1 = -1e30f;
#pragma unroll
        for (int nt = 0; nt < 8; nt++) {
            vmax0 = fmaxf(vmax0, fmaxf(sf[nt][0], sf[nt][1]));
            vmax1 = fmaxf(vmax1, fmaxf(sf[nt][2], sf[nt][3]));
        }
        vmax0 = fmaxf(vmax0, __shfl_xor_sync(0xffffffffu, vmax0, 1));
        vmax0 = fmaxf(vmax0, __shfl_xor_sync(0xffffffffu, vmax0, 2));
        vmax1 = fmaxf(vmax1, __shfl_xor_sync(0xffffffffu, vmax1, 1));
        vmax1 = fmaxf(vmax1, __shfl_xor_sync(0xffffffffu, vmax1, 2));
        float nm0 = fmaxf(mr0, vmax0), nm1 = fmaxf(mr1, vmax1);
        float al0 = fexp2(mr0 - nm0), al1 = fexp2(mr1 - nm1);
        mr0 = nm0; mr1 = nm1;

        uint32_t pA[4][4];
        float ps0 = 0.f, ps1 = 0.f;
#pragma unroll
        for (int t = 0; t < 4; t++) {
            float p00 = fexp2(sf[2 * t][0] - nm0), p01 = fexp2(sf[2 * t][1] - nm0);
            float p10 = fexp2(sf[2 * t][2] - nm1), p11 = fexp2(sf[2 * t][3] - nm1);
            float p20 = fexp2(sf[2 * t + 1][0] - nm0), p21 = fexp2(sf[2 * t + 1][1] - nm0);
            float p30 = fexp2(sf[2 * t + 1][2] - nm1), p31 = fexp2(sf[2 * t + 1][3] - nm1);
            uint32_t w0 = bf2(p00, p01), w1 = bf2(p10, p11);
            uint32_t w2 = bf2(p20, p21), w3 = bf2(p30, p31);
            pA[t][0] = w0; pA[t][1] = w1; pA[t][2] = w2; pA[t][3] = w3;
            ps0 += lof(w0) + hif(w0) + lof(w2) + hif(w2);
            ps1 += lof(w1) + hif(w1) + lof(w3) + hif(w3);
        }
        ps0 += __shfl_xor_sync(0xffffffffu, ps0, 1);
        ps0 += __shfl_xor_sync(0xffffffffu, ps0, 2);
        ps1 += __shfl_xor_sync(0xffffffffu, ps1, 1);
        ps1 += __shfl_xor_sync(0xffffffffu, ps1, 2);
        lr0 = lr0 * al0 + ps0;
        lr1 = lr1 * al1 + ps1;
#pragma unroll
        for (int n = 0; n < 6; n++) {
            of[n][0] *= al0; of[n][1] *= al0;
            of[n][2] *= al1; of[n][3] *= al1;
        }

        // ---- O += P V (V split-2 at kvb+16384) ----
#pragma unroll
        for (int t = 0; t < 4; t++) {
#pragma unroll
            for (int vs = 0; vs < 2; vs++) {
#pragma unroll
                for (int np = 0; np < 3; np++) {
                    int key = 16 * t + l15;
                    int ch = 2 * np + lhi;
                    uint32_t r[4];
                    ldmx4t(r, kvb + 16384 + vs * 8192 + key * 128 +
                              ((ch * 16) ^ ((key & 7) * 16)));
                    mma_bf16(of[2 * np], pA[t], r[0], r[1]);
                    mma_bf16(of[2 * np + 1], pA[t], r[2], r[3]);
                }
            }
        }
        __syncthreads();
    }

    // ---- epilogue: normalize + split-2 store to g_sC ----
    float inv0 = 1.f / lr0, inv1 = 1.f / lr1;
    int r0 = q0 + 16 * w + (lane >> 2), r1 = r0 + 8;
    int cb = head * 48 + (lane & 3) * 2;
#pragma unroll
    for (int n = 0; n < 6; n++) {
        split2_pair(g_sC, r0 * 384 + cb + n * 8, of[n][0] * inv0, of[n][1] * inv0);
        split2_pair(g_sC, r1 * 384 + cb + n * 8, of[n][2] * inv1, of[n][3] * inv1);
    }
}

// ---------------- output projection + sigmoid --------------------------------
__global__ __launch_bounds__(256) void k_out(const float* __restrict__ Wout,
                                             const float* __restrict__ bout,
                                             float* __restrict__ out) {
    int warp = (blockIdx.x * blockDim.x + threadIdx.x) >> 5;
    int lane = threadIdx.x & 31;
    if (warp >= Nn) return;
    const float4* hr = (const float4*)(g_h + warp * Dd);
    const float4* wr = (const float4*)Wout;
    float s = 0.f;
#pragma unroll
    for (int q = 0; q < 3; q++) {
        float4 a = hr[lane + 32 * q];
        float4 b = wr[lane + 32 * q];
        s += a.x * b.x + a.y * b.y + a.z * b.z + a.w * b.w;
    }
#pragma unroll
    for (int off = 16; off; off >>= 1)
        s += __shfl_xor_sync(0xffffffffu, s, off);
    if (lane == 0) out[warp] = 1.f / (1.f + __expf(-(s + bout[0])));
}

// ---------------- launch ------------------------------------------------------
extern "C" void kernel_launch(void* const* d_in, const int* in_sizes, int n_in,
                              void* d_out, int out_size) {
    const float* emb  = (const float*)d_in[0];
    const int*   ei   = (const int*)d_in[1];
    const float* Wc   = (const float*)d_in[2];
    const float* bc   = (const float*)d_in[3];
    const float* Win  = (const float*)d_in[4];
    const float* bin  = (const float*)d_in[5];
    const float* Wao  = (const float*)d_in[6];
    const float* bao  = (const float*)d_in[7];
    const float* Wout = (const float*)d_in[8];
    const float* bout = (const float*)d_in[9];
    float* out = (float*)d_out;

    cudaFuncSetAttribute(k_flash_mma, cudaFuncAttributeMaxDynamicSharedMemorySize,
                         FL_SMEM);
    cudaFuncSetAttribute(k_gemm_mma<0>, cudaFuncAttributeMaxDynamicSharedMemorySize,
                         GM_SMEM);
    cudaFuncSetAttribute(k_gemm_mma<1>, cudaFuncAttributeMaxDynamicSharedMemorySize,
                         GM_SMEM);
    cudaFuncSetAttribute(k_gemm_mma<2>, cudaFuncAttributeMaxDynamicSharedMemorySize,
                         GM_SMEM);

    // CSR build + weight splits (reused across all 3 layers)
    k_zero_deg<<<Nn / 256, 256>>>();
    k_hist<<<Ee / 256, 256>>>(ei);
    k_scan<<<1, 1024>>>();
    k_fill<<<Ee / 256, 256>>>(ei);
    k_copy<<<(Nn * Dd / 4) / 256, 256>>>(emb);
    k_wsplit<<<432, 256>>>(Wc, 0, 3 * Dd * Dd / 4);
    k_wsplit<<<432, 256>>>(Win, OFF_WIN, 3 * Dd * Dd / 4);
    k_wsplit<<<144, 256>>>(Wao, OFF_WAO, Dd * Dd / 4);

    for (int l = 0; l < Ll; l++) {
        k_gather<<<Nn / 8, 256>>>();
        k_gemm_mma<0><<<dim3(Dd / 64, Nn / 128), 256, GM_SMEM>>>(OFF_CONV(l),
                                                                 bc + l * Dd);
        k_gemm_mma<1><<<dim3(3 * Dd / 64, Nn / 128), 256, GM_SMEM>>>(OFF_WIN, bin);
        k_flash_mma<<<dim3(Nn / 128, Hh), 256, FL_SMEM>>>();
        k_gemm_mma<2><<<dim3(Dd / 64, Nn / 128), 256, GM_SMEM>>>(OFF_WAO, bao);
    }
    k_out<<<Nn / 8, 256>>>(Wout, bout, out);
}